// round 16
// baseline (speedup 1.0000x reference)
#include <cuda_runtime.h>
#include <cuda_fp16.h>
#include <math.h>
#include <stdint.h>

#define NNODES 50000
#define KNEI   32
#define DIM    128
#define DOUT   128
#define BM     128
#define BN     64

// gemm smem geometry (u32): A 128x36 (64 fp16 + pad), B 64x36
#define ASTR   36
#define B_OFF  (BM * ASTR)            // 4608
#define STG_U32 (B_OFF + BN * ASTR)   // 6912 (27648 B)
#define NSTAGE 4
#define NUNIT  8                      // 8 units x K=64 = 512

// Static device scratch (allowed).
__device__ __half g_f1h[(size_t)NNODES * DIM];   // fp16(fea1)
__device__ __half g_f2h[(size_t)NNODES * DIM];   // fp16(fea2)
__device__ __half g_n1h[(size_t)NNODES * DIM];   // fp16(mean nei1)
__device__ __half g_n2h[(size_t)NNODES * DIM];   // fp16(mean nei2)
__device__ __half g_Wh [(size_t)DOUT * 512];     // fp16(W), [n][k]

__device__ __forceinline__ uint32_t smem_u32p(const void* p) {
    uint32_t a;
    asm("{ .reg .u64 t; cvta.to.shared.u64 t, %1; cvt.u32.u64 %0, t; }" : "=r"(a) : "l"(p));
    return a;
}
__device__ __forceinline__ void cp_async16(uint32_t dst, const void* src) {
    asm volatile("cp.async.cg.shared.global [%0], [%1], 16;"
                 :: "r"(dst), "l"(src) : "memory");
}
#define CP_COMMIT() asm volatile("cp.async.commit_group;" ::: "memory")
#define CP_WAIT2()  asm volatile("cp.async.wait_group 2;"  ::: "memory")

__device__ __forceinline__ void mma_f16(float c[4], const uint32_t a[4],
                                        const uint32_t b[2]) {
    asm volatile(
        "mma.sync.aligned.m16n8k16.row.col.f32.f16.f16.f32 "
        "{%0,%1,%2,%3}, {%4,%5,%6,%7}, {%8,%9}, {%0,%1,%2,%3};"
        : "+f"(c[0]), "+f"(c[1]), "+f"(c[2]), "+f"(c[3])
        : "r"(a[0]), "r"(a[1]), "r"(a[2]), "r"(a[3]), "r"(b[0]), "r"(b[1]));
}
__device__ __forceinline__ void ldmatrix_x4(uint32_t& r0, uint32_t& r1,
                                            uint32_t& r2, uint32_t& r3,
                                            uint32_t addr) {
    asm volatile("ldmatrix.sync.aligned.m8n8.x4.shared.b16 {%0,%1,%2,%3}, [%4];"
                 : "=r"(r0), "=r"(r1), "=r"(r2), "=r"(r3) : "r"(addr));
}
__device__ __forceinline__ float tanh_approx(float x) {
    float r;
    asm("tanh.approx.f32 %0, %1;" : "=f"(r) : "f"(x));
    return r;
}

// ---------------------------------------------------------------------------
// conv: fea1 -> fp16 ; W -> fp16 [n][k] (transposed)
// ---------------------------------------------------------------------------
__global__ __launch_bounds__(256)
void conv_kernel(const float* __restrict__ fea1, const float* __restrict__ W) {
    const int t = blockIdx.x * 256 + threadIdx.x;   // 0..400127
    if (t < 400000) {
        #pragma unroll
        for (int h = 0; h < 2; h++) {
            size_t p = (size_t)t + (size_t)h * 400000;
            float4 a = reinterpret_cast<const float4*>(fea1)[2 * p];
            float4 b = reinterpret_cast<const float4*>(fea1)[2 * p + 1];
            __half2 p0 = __floats2half2_rn(a.x, a.y);
            __half2 p1 = __floats2half2_rn(a.z, a.w);
            __half2 p2 = __floats2half2_rn(b.x, b.y);
            __half2 p3 = __floats2half2_rn(b.z, b.w);
            uint4 o;
            o.x = *reinterpret_cast<uint32_t*>(&p0);
            o.y = *reinterpret_cast<uint32_t*>(&p1);
            o.z = *reinterpret_cast<uint32_t*>(&p2);
            o.w = *reinterpret_cast<uint32_t*>(&p3);
            reinterpret_cast<uint4*>(g_f1h)[p] = o;
        }
    }
    if (t < DOUT * 256) {
        int n  = t >> 8;
        int kp = t & 255;
        float w0 = W[(size_t)(2 * kp) * DOUT + n];
        float w1 = W[(size_t)(2 * kp + 1) * DOUT + n];
        __half2 p = __floats2half2_rn(w0, w1);
        reinterpret_cast<uint32_t*>(g_Wh)[n * 256 + kp] =
            *reinterpret_cast<uint32_t*>(&p);
    }
}

// ---------------------------------------------------------------------------
// agg: (a) fea2 -> fp16 slice (rides under L2-bound gather)
//      (b) one warp per node: fp16 gather, fp32 accum, fp16 means.
// ---------------------------------------------------------------------------
__global__ __launch_bounds__(256)
void agg_kernel(const float* __restrict__ fea2,
                const int* __restrict__ idx1, const int* __restrict__ idx2) {
    const int tid  = threadIdx.x;
    const int lane = tid & 31;

    {
        size_t p = (size_t)blockIdx.x * 256 + tid;
        float4 a = reinterpret_cast<const float4*>(fea2)[p];
        __half2 p0 = __floats2half2_rn(a.x, a.y);
        __half2 p1 = __floats2half2_rn(a.z, a.w);
        uint2 o;
        o.x = *reinterpret_cast<uint32_t*>(&p0);
        o.y = *reinterpret_cast<uint32_t*>(&p1);
        reinterpret_cast<uint2*>(g_f2h)[p] = o;
    }

    const int node = blockIdx.x * 8 + (tid >> 5);
    const uint2* fh = reinterpret_cast<const uint2*>(g_f1h);
    const float sc = 1.0f / (float)KNEI;

    #pragma unroll
    for (int list = 0; list < 2; list++) {
        const int* idx = list ? idx2 : idx1;
        __half* dst = list ? g_n2h : g_n1h;
        int myidx = idx[node * KNEI + lane];
        float4 a0 = make_float4(0.f, 0.f, 0.f, 0.f);
        float4 a1 = make_float4(0.f, 0.f, 0.f, 0.f);
        #pragma unroll
        for (int j = 0; j < KNEI; j += 2) {
            int i0 = __shfl_sync(0xffffffffu, myidx, j + 0);
            int i1 = __shfl_sync(0xffffffffu, myidx, j + 1);
            uint2 v0 = __ldg(&fh[(size_t)i0 * 32 + lane]);
            uint2 v1 = __ldg(&fh[(size_t)i1 * 32 + lane]);
            float2 l0 = __half22float2(*reinterpret_cast<__half2*>(&v0.x));
            float2 h0 = __half22float2(*reinterpret_cast<__half2*>(&v0.y));
            float2 l1 = __half22float2(*reinterpret_cast<__half2*>(&v1.x));
            float2 h1 = __half22float2(*reinterpret_cast<__half2*>(&v1.y));
            a0.x += l0.x; a0.y += l0.y; a0.z += h0.x; a0.w += h0.y;
            a1.x += l1.x; a1.y += l1.y; a1.z += h1.x; a1.w += h1.y;
        }
        __half2 m0 = __floats2half2_rn((a0.x + a1.x) * sc, (a0.y + a1.y) * sc);
        __half2 m1 = __floats2half2_rn((a0.z + a1.z) * sc, (a0.w + a1.w) * sc);
        uint2 o;
        o.x = *reinterpret_cast<uint32_t*>(&m0);
        o.y = *reinterpret_cast<uint32_t*>(&m1);
        *reinterpret_cast<uint2*>(&dst[(size_t)node * DIM + lane * 4]) = o;
    }
}

// ---------------------------------------------------------------------------
// gemm: out = tanh([f1|f2|n1|n2] @ W), fp16 m16n8k16.
// BM=128 x BN=64 tiles, grid 782 (bid>>1 = row tile, bid&1 = N half).
// 8 units x K=64, 4-stage cp.async pipeline (prefetch depth 3), ldmatrix.
// 8 warps as 4(M) x 2(N): each warp 32(M) x 32(N).
// ---------------------------------------------------------------------------
__global__ __launch_bounds__(256, 2)
void gemm_kernel(float* __restrict__ out) {
    extern __shared__ uint32_t smem[];

    const int tid  = threadIdx.x;
    const int wid  = tid >> 5;
    const int lane = tid & 31;
    const int gid  = lane >> 2;
    const int tig  = lane & 3;
    const int warp_m = (wid & 3) * 32;     // 0,32,64,96
    const int warp_n = (wid >> 2) * 32;    // 0,32
    const int block_row = (blockIdx.x >> 1) * BM;
    const int block_n   = (blockIdx.x & 1) * BN;
    const uint32_t sbase = smem_u32p(smem);

    const int a_row_l  = lane & 15;
    const int a_koff_l = (lane >> 4) * 4;
    const int b_col_l  = ((lane >> 4) << 3) + (lane & 7);
    const int b_koff_l = ((lane >> 3) & 1) * 4;

    auto load_unit = [&](int p, int stage) {
        const uint32_t aB = sbase + stage * (STG_U32 * 4);
        const uint32_t bB = aB + B_OFF * 4;
        const __half* srcs[4] = {g_f1h, g_f2h, g_n1h, g_n2h};
        const __half* A = srcs[p >> 1];
        const int colb = (p & 1) * 64;
        #pragma unroll
        for (int i = 0; i < 4; i++) {          // A: 128 rows x 8 segs
            int u  = tid + i * 256;
            int r  = u >> 3;
            int c4 = u & 7;
            int gr = block_row + r;
            if (gr >= NNODES) gr = NNODES - 1;
            cp_async16(aB + r * (ASTR * 4) + c4 * 16,
                       A + (size_t)gr * DIM + colb + c4 * 8);
        }
        const int kp0 = p * 32;
        #pragma unroll
        for (int i = 0; i < 2; i++) {          // B: 64 rows x 8 segs
            int u  = tid + i * 256;
            int r  = u >> 3;                   // 0..63
            int c4 = u & 7;
            cp_async16(bB + r * (ASTR * 4) + c4 * 16,
                       reinterpret_cast<const uint32_t*>(g_Wh) +
                           (size_t)(block_n + r) * 256 + kp0 + c4 * 4);
        }
    };

    float acc[2][4][4];
    #pragma unroll
    for (int mt = 0; mt < 2; mt++)
        #pragma unroll
        for (int nt = 0; nt < 4; nt++)
            #pragma unroll
            for (int i = 0; i < 4; i++)
                acc[mt][nt][i] = 0.f;

    load_unit(0, 0); CP_COMMIT();
    load_unit(1, 1); CP_COMMIT();
    load_unit(2, 2); CP_COMMIT();

    #pragma unroll 1
    for (int p = 0; p < NUNIT; p++) {
        CP_WAIT2();          // own group p arrived (<=2 groups pending)
        __syncthreads();     // everyone's group p arrived; all mma(p-1) done

        if (p + 3 < NUNIT) load_unit(p + 3, (p + 3) % NSTAGE);
        CP_COMMIT();

        const uint32_t aB = sbase + (p % NSTAGE) * (STG_U32 * 4);
        const uint32_t bB = aB + B_OFF * 4;

        #pragma unroll
        for (int ks = 0; ks < 4; ks++) {       // 4 x k16 = K64
            const int j = ks * 8;
            uint32_t af[2][4];
            #pragma unroll
            for (int mt = 0; mt < 2; mt++) {
                int row = warp_m + mt * 16 + a_row_l;
                ldmatrix_x4(af[mt][0], af[mt][1], af[mt][2], af[mt][3],
                            aB + (row * ASTR + j + a_koff_l) * 4);
            }
            uint32_t bf[4][2];
            #pragma unroll
            for (int q = 0; q < 2; q++) {      // 2 nt per ldmatrix.x4
                int col = warp_n + q * 16 + b_col_l;
                ldmatrix_x4(bf[2 * q][0], bf[2 * q][1],
                            bf[2 * q + 1][0], bf[2 * q + 1][1],
                            bB + (col * ASTR + j + b_koff_l) * 4);
            }
            #pragma unroll
            for (int mt = 0; mt < 2; mt++)
                #pragma unroll
                for (int nt = 0; nt < 4; nt++)
                    mma_f16(acc[mt][nt], af[mt], bf[nt]);
        }
    }

    // epilogue: HW tanh + store
    #pragma unroll
    for (int mt = 0; mt < 2; mt++) {
        #pragma unroll
        for (int half = 0; half < 2; half++) {
            int gr = block_row + warp_m + mt * 16 + gid + half * 8;
            if (gr < NNODES) {
                #pragma unroll
                for (int nt = 0; nt < 4; nt++) {
                    float2 v;
                    v.x = tanh_approx(acc[mt][nt][half * 2 + 0]);
                    v.y = tanh_approx(acc[mt][nt][half * 2 + 1]);
                    *reinterpret_cast<float2*>(
                        out + (size_t)gr * DOUT + block_n + warp_n + nt * 8 + tig * 2) = v;
                }
            }
        }
    }
}

// ---------------------------------------------------------------------------
extern "C" void kernel_launch(void* const* d_in, const int* in_sizes, int n_in,
                              void* d_out, int out_size) {
    const float* node_fea1 = (const float*)d_in[0];
    const float* node_fea2 = (const float*)d_in[1];
    const int*   neigh1    = (const int*)  d_in[2];
    const int*   neigh2    = (const int*)  d_in[3];
    const float* weight    = (const float*)d_in[4];
    float*       out       = (float*)d_out;

    const int dyn_smem = NSTAGE * STG_U32 * 4;   // 110592 B
    static bool attr_set = false;
    if (!attr_set) {
        cudaFuncSetAttribute(gemm_kernel,
                             cudaFuncAttributeMaxDynamicSharedMemorySize, dyn_smem);
        attr_set = true;
    }

    conv_kernel<<<(400128 + 255) / 256, 256>>>(node_fea1, weight);
    agg_kernel<<<NNODES / 8, 256>>>(node_fea2, neigh1, neigh2);
    gemm_kernel<<<((NNODES + BM - 1) / BM) * 2, 256, dyn_smem>>>(out);
}

// round 17
// speedup vs baseline: 1.0682x; 1.0682x over previous
#include <cuda_runtime.h>
#include <cuda_fp16.h>
#include <math.h>
#include <stdint.h>

#define NNODES 50000
#define KNEI   32
#define DIM    128
#define DOUT   128
#define BM     128

// gemm smem geometry (u32): A 128x36 (64 fp16 + pad), B 128x36
#define ASTR   36
#define B_OFF  (BM * ASTR)            // 4608
#define STG_U32 (2 * BM * ASTR)       // 9216
#define NSTAGE 3
#define NUNIT  8                      // 8 units x K=64 = 512

// Static device scratch (allowed).
__device__ __half g_f1h[(size_t)NNODES * DIM];   // fp16(fea1)
__device__ __half g_f2h[(size_t)NNODES * DIM];   // fp16(fea2)
__device__ __half g_n1h[(size_t)NNODES * DIM];   // fp16(mean nei1)
__device__ __half g_n2h[(size_t)NNODES * DIM];   // fp16(mean nei2)
__device__ __half g_Wh [(size_t)DOUT * 512];     // fp16(W), [n][k]

__device__ __forceinline__ uint32_t smem_u32p(const void* p) {
    uint32_t a;
    asm("{ .reg .u64 t; cvta.to.shared.u64 t, %1; cvt.u32.u64 %0, t; }" : "=r"(a) : "l"(p));
    return a;
}
__device__ __forceinline__ void cp_async16(uint32_t dst, const void* src) {
    asm volatile("cp.async.cg.shared.global [%0], [%1], 16;"
                 :: "r"(dst), "l"(src) : "memory");
}
#define CP_COMMIT() asm volatile("cp.async.commit_group;" ::: "memory")
#define CP_WAIT1()  asm volatile("cp.async.wait_group 1;"  ::: "memory")

__device__ __forceinline__ void mma_f16(float c[4], const uint32_t a[4],
                                        const uint32_t b[2]) {
    asm volatile(
        "mma.sync.aligned.m16n8k16.row.col.f32.f16.f16.f32 "
        "{%0,%1,%2,%3}, {%4,%5,%6,%7}, {%8,%9}, {%0,%1,%2,%3};"
        : "+f"(c[0]), "+f"(c[1]), "+f"(c[2]), "+f"(c[3])
        : "r"(a[0]), "r"(a[1]), "r"(a[2]), "r"(a[3]), "r"(b[0]), "r"(b[1]));
}
__device__ __forceinline__ void ldmatrix_x4(uint32_t& r0, uint32_t& r1,
                                            uint32_t& r2, uint32_t& r3,
                                            uint32_t addr) {
    asm volatile("ldmatrix.sync.aligned.m8n8.x4.shared.b16 {%0,%1,%2,%3}, [%4];"
                 : "=r"(r0), "=r"(r1), "=r"(r2), "=r"(r3) : "r"(addr));
}
__device__ __forceinline__ float tanh_approx(float x) {
    float r;
    asm("tanh.approx.f32 %0, %1;" : "=f"(r) : "f"(x));
    return r;
}

// ---------------------------------------------------------------------------
// conv: fea1 -> fp16 (8 consecutive floats/thread, grid 3125) ;
//       W -> fp16 [n][k] (transposed)
// ---------------------------------------------------------------------------
__global__ __launch_bounds__(256)
void conv_kernel(const float* __restrict__ fea1, const float* __restrict__ W) {
    const int t = blockIdx.x * 256 + threadIdx.x;   // 0..799999
    {
        float4 a = reinterpret_cast<const float4*>(fea1)[2 * (size_t)t];
        float4 b = reinterpret_cast<const float4*>(fea1)[2 * (size_t)t + 1];
        __half2 p0 = __floats2half2_rn(a.x, a.y);
        __half2 p1 = __floats2half2_rn(a.z, a.w);
        __half2 p2 = __floats2half2_rn(b.x, b.y);
        __half2 p3 = __floats2half2_rn(b.z, b.w);
        uint4 o;
        o.x = *reinterpret_cast<uint32_t*>(&p0);
        o.y = *reinterpret_cast<uint32_t*>(&p1);
        o.z = *reinterpret_cast<uint32_t*>(&p2);
        o.w = *reinterpret_cast<uint32_t*>(&p3);
        reinterpret_cast<uint4*>(g_f1h)[t] = o;
    }
    if (t < DOUT * 256) {          // W transpose: 32768 threads, 2 k's each
        int n  = t >> 8;
        int kp = t & 255;
        float w0 = W[(size_t)(2 * kp) * DOUT + n];
        float w1 = W[(size_t)(2 * kp + 1) * DOUT + n];
        __half2 p = __floats2half2_rn(w0, w1);
        reinterpret_cast<uint32_t*>(g_Wh)[n * 256 + kp] =
            *reinterpret_cast<uint32_t*>(&p);
    }
}

// ---------------------------------------------------------------------------
// agg: (a) fea2 -> fp16 slice (rides under L2-bound gather)
//      (b) one warp per node: fp16 gather, fp32 accum, fp16 means.
// ---------------------------------------------------------------------------
__global__ __launch_bounds__(256)
void agg_kernel(const float* __restrict__ fea2,
                const int* __restrict__ idx1, const int* __restrict__ idx2) {
    const int tid  = threadIdx.x;
    const int lane = tid & 31;

    {
        size_t p = (size_t)blockIdx.x * 256 + tid;   // float4 index, exact
        float4 a = reinterpret_cast<const float4*>(fea2)[p];
        __half2 p0 = __floats2half2_rn(a.x, a.y);
        __half2 p1 = __floats2half2_rn(a.z, a.w);
        uint2 o;
        o.x = *reinterpret_cast<uint32_t*>(&p0);
        o.y = *reinterpret_cast<uint32_t*>(&p1);
        reinterpret_cast<uint2*>(g_f2h)[p] = o;
    }

    const int node = blockIdx.x * 8 + (tid >> 5);
    const uint2* fh = reinterpret_cast<const uint2*>(g_f1h);
    const float sc = 1.0f / (float)KNEI;

    #pragma unroll
    for (int list = 0; list < 2; list++) {
        const int* idx = list ? idx2 : idx1;
        __half* dst = list ? g_n2h : g_n1h;
        int myidx = idx[node * KNEI + lane];
        float4 a0 = make_float4(0.f, 0.f, 0.f, 0.f);
        float4 a1 = make_float4(0.f, 0.f, 0.f, 0.f);
        #pragma unroll
        for (int j = 0; j < KNEI; j += 2) {
            int i0 = __shfl_sync(0xffffffffu, myidx, j + 0);
            int i1 = __shfl_sync(0xffffffffu, myidx, j + 1);
            uint2 v0 = __ldg(&fh[(size_t)i0 * 32 + lane]);
            uint2 v1 = __ldg(&fh[(size_t)i1 * 32 + lane]);
            float2 l0 = __half22float2(*reinterpret_cast<__half2*>(&v0.x));
            float2 h0 = __half22float2(*reinterpret_cast<__half2*>(&v0.y));
            float2 l1 = __half22float2(*reinterpret_cast<__half2*>(&v1.x));
            float2 h1 = __half22float2(*reinterpret_cast<__half2*>(&v1.y));
            a0.x += l0.x; a0.y += l0.y; a0.z += h0.x; a0.w += h0.y;
            a1.x += l1.x; a1.y += l1.y; a1.z += h1.x; a1.w += h1.y;
        }
        __half2 m0 = __floats2half2_rn((a0.x + a1.x) * sc, (a0.y + a1.y) * sc);
        __half2 m1 = __floats2half2_rn((a0.z + a1.z) * sc, (a0.w + a1.w) * sc);
        uint2 o;
        o.x = *reinterpret_cast<uint32_t*>(&m0);
        o.y = *reinterpret_cast<uint32_t*>(&m1);
        *reinterpret_cast<uint2*>(&dst[(size_t)node * DIM + lane * 4]) = o;
    }
}

// ---------------------------------------------------------------------------
// gemm: out = tanh([f1|f2|n1|n2] @ W), fp16 m16n8k16, BM=128 (grid 391),
// 8 units x K=64, 3-stage cp.async pipeline, ldmatrix, single barrier/unit.
// Row clamp hoisted out of the per-segment path for full tiles.
// ---------------------------------------------------------------------------
__global__ __launch_bounds__(256, 2)
void gemm_kernel(float* __restrict__ out) {
    extern __shared__ uint32_t smem[];

    const int tid  = threadIdx.x;
    const int wid  = tid >> 5;
    const int lane = tid & 31;
    const int gid  = lane >> 2;
    const int tig  = lane & 3;
    const int warp_m = (wid >> 2) * 64;
    const int warp_n = (wid & 3) * 32;
    const int block_row = blockIdx.x * BM;
    const bool full_tile = (block_row + BM <= NNODES);
    const uint32_t sbase = smem_u32p(smem);

    const int a_row_l  = lane & 15;
    const int a_koff_l = (lane >> 4) * 4;
    const int b_col_l  = ((lane >> 4) << 3) + (lane & 7);
    const int b_koff_l = ((lane >> 3) & 1) * 4;

    auto load_unit = [&](int p, int stage) {
        const uint32_t aB = sbase + stage * (STG_U32 * 4);
        const uint32_t bB = aB + B_OFF * 4;
        const __half* srcs[4] = {g_f1h, g_f2h, g_n1h, g_n2h};
        const __half* A = srcs[p >> 1];
        const int colb = (p & 1) * 64;
        if (full_tile) {
            #pragma unroll
            for (int i = 0; i < 4; i++) {
                int u  = tid + i * 256;
                int r  = u >> 3;
                int c4 = u & 7;
                cp_async16(aB + r * (ASTR * 4) + c4 * 16,
                           A + (size_t)(block_row + r) * DIM + colb + c4 * 8);
            }
        } else {
            #pragma unroll
            for (int i = 0; i < 4; i++) {
                int u  = tid + i * 256;
                int r  = u >> 3;
                int c4 = u & 7;
                int gr = block_row + r;
                if (gr >= NNODES) gr = NNODES - 1;
                cp_async16(aB + r * (ASTR * 4) + c4 * 16,
                           A + (size_t)gr * DIM + colb + c4 * 8);
            }
        }
        const int kp0 = p * 32;
        #pragma unroll
        for (int i = 0; i < 4; i++) {
            int u  = tid + i * 256;
            int r  = u >> 3;
            int c4 = u & 7;
            cp_async16(bB + r * (ASTR * 4) + c4 * 16,
                       reinterpret_cast<const uint32_t*>(g_Wh) +
                           (size_t)r * 256 + kp0 + c4 * 4);
        }
    };

    float acc[4][4][4];
    #pragma unroll
    for (int mt = 0; mt < 4; mt++)
        #pragma unroll
        for (int nt = 0; nt < 4; nt++)
            #pragma unroll
            for (int i = 0; i < 4; i++)
                acc[mt][nt][i] = 0.f;

    load_unit(0, 0); CP_COMMIT();
    load_unit(1, 1); CP_COMMIT();

    #pragma unroll 1
    for (int p = 0; p < NUNIT; p++) {
        CP_WAIT1();          // own group p arrived
        __syncthreads();     // everyone's group p arrived; all mma(p-1) done

        if (p + 2 < NUNIT) load_unit(p + 2, (p + 2) % NSTAGE);
        CP_COMMIT();

        const uint32_t aB = sbase + (p % NSTAGE) * (STG_U32 * 4);
        const uint32_t bB = aB + B_OFF * 4;

        #pragma unroll
        for (int ks = 0; ks < 4; ks++) {       // 4 x k16 = K64
            const int j = ks * 8;
            uint32_t af[4][4];
            #pragma unroll
            for (int mt = 0; mt < 4; mt++) {
                int row = warp_m + mt * 16 + a_row_l;
                ldmatrix_x4(af[mt][0], af[mt][1], af[mt][2], af[mt][3],
                            aB + (row * ASTR + j + a_koff_l) * 4);
            }
            uint32_t bf[4][2];
            #pragma unroll
            for (int q = 0; q < 2; q++) {
                int col = warp_n + q * 16 + b_col_l;
                ldmatrix_x4(bf[2 * q][0], bf[2 * q][1],
                            bf[2 * q + 1][0], bf[2 * q + 1][1],
                            bB + (col * ASTR + j + b_koff_l) * 4);
            }
            #pragma unroll
            for (int mt = 0; mt < 4; mt++)
                #pragma unroll
                for (int nt = 0; nt < 4; nt++)
                    mma_f16(acc[mt][nt], af[mt], bf[nt]);
        }
    }

    // epilogue: HW tanh + store
    #pragma unroll
    for (int mt = 0; mt < 4; mt++) {
        #pragma unroll
        for (int half = 0; half < 2; half++) {
            int gr = block_row + warp_m + mt * 16 + gid + half * 8;
            if (gr < NNODES) {
                #pragma unroll
                for (int nt = 0; nt < 4; nt++) {
                    float2 v;
                    v.x = tanh_approx(acc[mt][nt][half * 2 + 0]);
                    v.y = tanh_approx(acc[mt][nt][half * 2 + 1]);
                    *reinterpret_cast<float2*>(
                        out + (size_t)gr * DOUT + warp_n + nt * 8 + tig * 2) = v;
                }
            }
        }
    }
}

// ---------------------------------------------------------------------------
extern "C" void kernel_launch(void* const* d_in, const int* in_sizes, int n_in,
                              void* d_out, int out_size) {
    const float* node_fea1 = (const float*)d_in[0];
    const float* node_fea2 = (const float*)d_in[1];
    const int*   neigh1    = (const int*)  d_in[2];
    const int*   neigh2    = (const int*)  d_in[3];
    const float* weight    = (const float*)d_in[4];
    float*       out       = (float*)d_out;

    const int dyn_smem = NSTAGE * STG_U32 * 4;   // 110592 B
    static bool attr_set = false;
    if (!attr_set) {
        cudaFuncSetAttribute(gemm_kernel,
                             cudaFuncAttributeMaxDynamicSharedMemorySize, dyn_smem);
        attr_set = true;
    }

    conv_kernel<<<3125, 256>>>(node_fea1, weight);
    agg_kernel<<<NNODES / 8, 256>>>(node_fea2, neigh1, neigh2);
    gemm_kernel<<<(NNODES + BM - 1) / BM, 256, dyn_smem>>>(out);
}